// round 16
// baseline (speedup 1.0000x reference)
#include <cuda_runtime.h>
#include <cuda_fp16.h>
#include <cstdint>

#define Bb 8
#define Nn_ 1024
#define Dd 1024
#define Hh 16
#define HD 64
#define QSCALE 0.125f   // 64^-0.5, exact power of two

// Scratch (device globals: no allocations allowed)
__device__ __half g_x16[Bb * Nn_ * Dd];        // x fp16 [row][k]
__device__ __half g_wq16t[3 * Dd * Dd];        // W_qkv fp16 TRANSPOSED [n][k]
__device__ __half g_wo16t[Dd * Dd];            // W_o  fp16 TRANSPOSED [n][k]
__device__ __half g_q16[Bb * Hh * Nn_ * HD];   // Q fp16 [bh][n][d], pre-scaled
__device__ __half g_k16[Bb * Hh * Nn_ * HD];   // K fp16 [bh][n][d]
__device__ __half g_v16[Bb * Hh * Nn_ * HD];   // V fp16 [bh][d][n]  (d-major!)
__device__ __half g_heads16[Bb * Nn_ * Dd];    // heads fp16 [b][n][h*HD+d]

// ---------------------------------------------------------------------------
// helpers
// ---------------------------------------------------------------------------
__device__ __forceinline__ uint32_t pkh(float a, float b) {   // {lo=a, hi=b}
    uint32_t r;
    asm("cvt.rn.f16x2.f32 %0, %1, %2;" : "=r"(r) : "f"(b), "f"(a));
    return r;
}

__device__ __forceinline__ void mma_f16(float c[4],
                                        uint32_t a0, uint32_t a1,
                                        uint32_t a2, uint32_t a3,
                                        uint32_t b0, uint32_t b1) {
    asm volatile(
        "mma.sync.aligned.m16n8k16.row.col.f32.f16.f16.f32 "
        "{%0,%1,%2,%3}, {%4,%5,%6,%7}, {%8,%9}, {%0,%1,%2,%3};"
        : "+f"(c[0]), "+f"(c[1]), "+f"(c[2]), "+f"(c[3])
        : "r"(a0), "r"(a1), "r"(a2), "r"(a3), "r"(b0), "r"(b1));
}

__device__ __forceinline__ uint32_t s2u(const void* p) {
    return (uint32_t)__cvta_generic_to_shared(p);
}

__device__ __forceinline__ void ldsm_x4(uint32_t& r0, uint32_t& r1,
                                        uint32_t& r2, uint32_t& r3,
                                        uint32_t addr) {
    asm volatile("ldmatrix.sync.aligned.m8n8.x4.shared.b16 {%0,%1,%2,%3}, [%4];"
                 : "=r"(r0), "=r"(r1), "=r"(r2), "=r"(r3) : "r"(addr));
}

// ---------------------------------------------------------------------------
// Prologue: x -> fp16 (elementwise; 8 floats per thread)
// ---------------------------------------------------------------------------
__global__ __launch_bounds__(256)
void cvt_x_kernel(const float4* __restrict__ in)
{
    int i = blockIdx.x * blockDim.x + threadIdx.x;   // 0 .. 1M-1
    float4 v0 = in[2 * i];
    float4 v1 = in[2 * i + 1];
    ((uint4*)g_x16)[i] = make_uint4(pkh(v0.x, v0.y), pkh(v0.z, v0.w),
                                    pkh(v1.x, v1.y), pkh(v1.z, v1.w));
}

// ---------------------------------------------------------------------------
// Prologue: W [K][N] fp32 -> Wt [N][K] fp16 (tiled transpose)
// which: 1 -> g_wq16t, 2 -> g_wo16t
// ---------------------------------------------------------------------------
__global__ __launch_bounds__(256)
void wt_kernel(const float* __restrict__ W, int N, int Kdim, int which)
{
    __shared__ __half t[32][33];
    __half* Wt = (which == 1) ? g_wq16t : g_wo16t;

    const int n0 = blockIdx.x * 32;
    const int k0 = blockIdx.y * 32;
    const int tx = threadIdx.x & 31;
    const int ty = threadIdx.x >> 5;      // 0..7

#pragma unroll
    for (int i = 0; i < 32; i += 8)
        t[ty + i][tx] = __float2half_rn(W[(size_t)(k0 + ty + i) * N + n0 + tx]);
    __syncthreads();
#pragma unroll
    for (int i = 0; i < 32; i += 8)
        Wt[(size_t)(n0 + ty + i) * Kdim + k0 + tx] = t[tx][ty + i];
}

// ---------------------------------------------------------------------------
// fp16 tensor-core GEMM, software-pipelined, warp tile 64x64.
// Block tile 256x128, BK=32, 256 threads = 8 warps (4M x 2N).
// Per k16-chunk per warp: 4 A-LDSM.x4 + 4 B-LDSM.x4 -> 32 MMAs
// (0.25 LDSM/MMA vs 0.375 before: targets the L1TEX=80% bottleneck).
// Dynamic smem 61,440 B: Ah[2][256][40] + Bh[2][128][40].
// MODE 1: A=g_x16, W=g_wq16t; QKV scatter epilogue (q scaled; V d-major)
// MODE 2: A=g_heads16, W=g_wo16t; fp32 C + bias
// ---------------------------------------------------------------------------
#define GEMM_SMEM_BYTES ((2 * 256 * 40 + 2 * 128 * 40) * 2)

template <int MODE>
__global__ __launch_bounds__(256)
void sgemm_kernel(const float* __restrict__ bias,
                  float* __restrict__ C,
                  int M, int N, int K)
{
    extern __shared__ __half sh[];
    __half* Ah = sh;                       // [2][256][40]
    __half* Bh = sh + 2 * 256 * 40;        // [2][128][40]

    const __half* __restrict__ A16 = (MODE == 1) ? g_x16    : g_heads16;
    const __half* __restrict__ Wt  = (MODE == 1) ? g_wq16t  : g_wo16t;

    const int tid  = threadIdx.x;
    const int lane = tid & 31;
    const int warp = tid >> 5;
    const int warpM = warp >> 1;           // 0..3
    const int warpN = warp & 1;            // 0..1

    const int r0 = blockIdx.y * 256;
    const int c0 = blockIdx.x * 128;

    // A loader: 1 thread per row, 32 halves (4 uint4)
    const int a_row = tid;
    // B loader: 2 threads per row, 16 halves (2 uint4)
    const int b_row = tid >> 1;
    const int b_kc  = (tid & 1) * 16;

    const __half* Aptr = A16 + (size_t)(r0 + a_row) * K;
    const __half* Bptr = Wt + (size_t)(c0 + b_row) * K + b_kc;

    // ldmatrix lane constants
    const int l15   = lane & 15;
    const int lcoff = (lane >> 4) * 8;
    const int brow  = (lane & 7) + ((lane >> 4) << 3);
    const int bcoff = ((lane >> 3) & 1) * 8;

    float acc[4][8][4];
#pragma unroll
    for (int i = 0; i < 4; i++)
#pragma unroll
        for (int j = 0; j < 8; j++)
#pragma unroll
            for (int r = 0; r < 4; r++) acc[i][j][r] = 0.0f;

    const int lr = lane >> 2;
    const int lc = lane & 3;

    uint4 pa0, pa1, pa2, pa3, pb0, pb1;

#define GLOAD(k0) do {                                                      \
        pa0 = *(const uint4*)(Aptr + (k0));                                 \
        pa1 = *(const uint4*)(Aptr + (k0) + 8);                             \
        pa2 = *(const uint4*)(Aptr + (k0) + 16);                            \
        pa3 = *(const uint4*)(Aptr + (k0) + 24);                            \
        pb0 = *(const uint4*)(Bptr + (k0));                                 \
        pb1 = *(const uint4*)(Bptr + (k0) + 8);                             \
    } while (0)

#define SSTORE(buf) do {                                                    \
        __half* da = Ah + (buf) * (256 * 40) + a_row * 40;                  \
        *(uint4*)(da)      = pa0;                                           \
        *(uint4*)(da + 8)  = pa1;                                           \
        *(uint4*)(da + 16) = pa2;                                           \
        *(uint4*)(da + 24) = pa3;                                           \
        __half* db = Bh + (buf) * (128 * 40) + b_row * 40 + b_kc;           \
        *(uint4*)(db)     = pb0;                                            \
        *(uint4*)(db + 8) = pb1;                                            \
    } while (0)

    GLOAD(0);
    SSTORE(0);
    __syncthreads();

    const int NS = K / 32;
    int buf = 0;
    for (int stage = 0; stage < NS; stage++) {
        if (stage + 1 < NS) GLOAD((stage + 1) * 32);

        const __half* Ax = Ah + buf * (256 * 40);
        const __half* Bx = Bh + buf * (128 * 40);

#pragma unroll
        for (int kk = 0; kk < 32; kk += 16) {
            uint32_t af[4][4];
#pragma unroll
            for (int am = 0; am < 4; am++)
                ldsm_x4(af[am][0], af[am][1], af[am][2], af[am][3],
                        s2u(Ax + (warpM * 64 + am * 16 + l15) * 40 + kk + lcoff));
#pragma unroll
            for (int g = 0; g < 4; g++) {
                uint32_t b0, b1, b2, b3;
                ldsm_x4(b0, b1, b2, b3,
                        s2u(Bx + (warpN * 64 + g * 16 + brow) * 40 + kk + bcoff));
#pragma unroll
                for (int am = 0; am < 4; am++) {
                    mma_f16(acc[am][2 * g],     af[am][0], af[am][1], af[am][2],
                            af[am][3], b0, b1);
                    mma_f16(acc[am][2 * g + 1], af[am][0], af[am][1], af[am][2],
                            af[am][3], b2, b3);
                }
            }
        }

        if (stage + 1 < NS) SSTORE(buf ^ 1);
        __syncthreads();
        buf ^= 1;
    }
#undef GLOAD
#undef SSTORE

    // ---- epilogue ----
#pragma unroll
    for (int am = 0; am < 4; am++) {
        const int row0 = r0 + warpM * 64 + am * 16 + lr;
        const int row1 = row0 + 8;
#pragma unroll
        for (int bn = 0; bn < 8; bn++) {
            const int atomcol = c0 + warpN * 64 + bn * 8;
            const int colp = atomcol + lc * 2;
            const float b0v = bias[colp];
            const float b1v = bias[colp + 1];
            float v00 = acc[am][bn][0] + b0v, v01 = acc[am][bn][1] + b1v;
            float v10 = acc[am][bn][2] + b0v, v11 = acc[am][bn][3] + b1v;

            if (MODE == 2) {
                *(float2*)(C + (size_t)row0 * N + colp) = make_float2(v00, v01);
                *(float2*)(C + (size_t)row1 * N + colp) = make_float2(v10, v11);
            } else {
                const int h     = atomcol / 192;
                const int rem   = atomcol % 192;
                const int t     = rem / 64;          // 0=q 1=k 2=v
                const int dbase = (rem % 64) + lc * 2;
                const int b0r = row0 >> 10, n0 = row0 & 1023;
                const int b1r = row1 >> 10, n1 = row1 & 1023;

                if (t == 2) {
                    const size_t vb0 = ((size_t)(b0r * Hh + h) * HD + dbase) * Nn_;
                    const size_t vb1 = ((size_t)(b1r * Hh + h) * HD + dbase) * Nn_;
                    g_v16[vb0 + n0]       = __float2half_rn(v00);
                    g_v16[vb0 + Nn_ + n0] = __float2half_rn(v01);
                    g_v16[vb1 + n1]       = __float2half_rn(v10);
                    g_v16[vb1 + Nn_ + n1] = __float2half_rn(v11);
                } else {
                    __half* dst = (t == 0) ? g_q16 : g_k16;
                    const float sc = (t == 0) ? QSCALE : 1.0f;
                    const size_t off0 = (((size_t)(b0r * Hh + h) << 10) + n0) * HD + dbase;
                    const size_t off1 = (((size_t)(b1r * Hh + h) << 10) + n1) * HD + dbase;
                    *(uint32_t*)(dst + off0) = pkh(v00 * sc, v01 * sc);
                    *(uint32_t*)(dst + off1) = pkh(v10 * sc, v11 * sc);
                }
            }
        }
    }
}

// ---------------------------------------------------------------------------
// fp16 tensor-core flash attention (UNCHANGED from R15 -- passing).
// ---------------------------------------------------------------------------
__global__ __launch_bounds__(128, 4)
void attn_mma_kernel()
{
    __shared__ __half Qs[64][72];
    __shared__ __half Ks[32][72];
    __shared__ __half Vs[64][40];
    __shared__ __half Ps[64][40];

    const int tid  = threadIdx.x;
    const int lane = tid & 31;
    const int warp = tid >> 5;
    const int lr   = lane >> 2;
    const int lc   = lane & 3;

    const int bh = blockIdx.y;
    const int r0 = blockIdx.x * 64;
    const int b  = bh >> 4;
    const int h  = bh & 15;

    const __half* qg = g_q16 + (size_t)bh * Nn_ * HD;    // [n][d]
    const __half* kg = g_k16 + (size_t)bh * Nn_ * HD;    // [n][d]
    const __half* vg = g_v16 + (size_t)bh * HD * Nn_;    // [d][n]

    const int l15   = lane & 15;
    const int lcoff = (lane >> 4) * 8;
    const int brow  = (lane & 7) + ((lane >> 4) << 3);
    const int bcoff = ((lane >> 3) & 1) * 8;

#pragma unroll
    for (int i = 0; i < 4; i++) {
        int idx4 = i * 128 + tid;
        int row  = idx4 >> 3;
        int c8   = (idx4 & 7) * 8;
        *(uint4*)&Qs[row][c8] = *(const uint4*)(qg + (size_t)(r0 + row) * HD + c8);
    }

    float oacc[8][4];
#pragma unroll
    for (int bn = 0; bn < 8; bn++)
#pragma unroll
        for (int r = 0; r < 4; r++) oacc[bn][r] = 0.0f;
    float m0 = -3.0e38f, m1 = -3.0e38f, l0 = 0.0f, l1 = 0.0f;

    const int wrow = warp * 16;

    __syncthreads();

    for (int kt = 0; kt < Nn_ / 32; kt++) {
        const int c0 = kt * 32;

#pragma unroll
        for (int i = 0; i < 2; i++) {
            int idx4 = i * 128 + tid;
            int row  = idx4 >> 3;
            int c8   = (idx4 & 7) * 8;
            *(uint4*)&Ks[row][c8] =
                *(const uint4*)(kg + (size_t)(c0 + row) * HD + c8);
        }
#pragma unroll
        for (int i = 0; i < 2; i++) {
            int idx4 = i * 128 + tid;
            int d    = idx4 >> 2;
            int s8   = (idx4 & 3) * 8;
            *(uint4*)&Vs[d][s8] =
                *(const uint4*)(vg + (size_t)d * Nn_ + c0 + s8);
        }
        __syncthreads();

        float sacc[4][4];
#pragma unroll
        for (int bn = 0; bn < 4; bn++)
#pragma unroll
            for (int r = 0; r < 4; r++) sacc[bn][r] = 0.0f;

#pragma unroll
        for (int kk = 0; kk < 64; kk += 16) {
            uint32_t a0, a1, a2, a3;
            ldsm_x4(a0, a1, a2, a3, s2u(&Qs[wrow + l15][kk + lcoff]));
            uint32_t k0r, k1r, k2r, k3r;
            ldsm_x4(k0r, k1r, k2r, k3r, s2u(&Ks[brow][kk + bcoff]));
            mma_f16(sacc[0], a0, a1, a2, a3, k0r, k1r);
            mma_f16(sacc[1], a0, a1, a2, a3, k2r, k3r);
            ldsm_x4(k0r, k1r, k2r, k3r, s2u(&Ks[16 + brow][kk + bcoff]));
            mma_f16(sacc[2], a0, a1, a2, a3, k0r, k1r);
            mma_f16(sacc[3], a0, a1, a2, a3, k2r, k3r);
        }

        float rmax0 = -3.0e38f, rmax1 = -3.0e38f;
#pragma unroll
        for (int bn = 0; bn < 4; bn++) {
            rmax0 = fmaxf(rmax0, fmaxf(sacc[bn][0], sacc[bn][1]));
            rmax1 = fmaxf(rmax1, fmaxf(sacc[bn][2], sacc[bn][3]));
        }
        rmax0 = fmaxf(rmax0, __shfl_xor_sync(0xffffffffu, rmax0, 1));
        rmax0 = fmaxf(rmax0, __shfl_xor_sync(0xffffffffu, rmax0, 2));
        rmax1 = fmaxf(rmax1, __shfl_xor_sync(0xffffffffu, rmax1, 1));
        rmax1 = fmaxf(rmax1, __shfl_xor_sync(0xffffffffu, rmax1, 2));

        const float newm0 = fmaxf(m0, rmax0);
        const float newm1 = fmaxf(m1, rmax1);
        const float fac0  = __expf(m0 - newm0);
        const float fac1  = __expf(m1 - newm1);

        float p[4][4];
        float rsum0 = 0.0f, rsum1 = 0.0f;
#pragma unroll
        for (int bn = 0; bn < 4; bn++) {
            p[bn][0] = __expf(sacc[bn][0] - newm0);
            p[bn][1] = __expf(sacc[bn][1] - newm0);
            p[bn][2] = __expf(sacc[bn][2] - newm1);
            p[bn][3] = __expf(sacc[bn][3] - newm1);
            rsum0 += p[bn][0] + p[bn][1];
            rsum1 += p[bn][2] + p[bn][3];
        }
        rsum0 += __shfl_xor_sync(0xffffffffu, rsum0, 1);
        rsum0 += __shfl_xor_sync(0xffffffffu, rsum0, 2);
        rsum1 += __shfl_xor_sync(0xffffffffu, rsum1, 1);
        rsum1 += __shfl_xor_sync(0xffffffffu, rsum1, 2);

        l0 = l0 * fac0 + rsum0;  m0 = newm0;
        l1 = l1 * fac1 + rsum1;  m1 = newm1;
#pragma unroll
        for (int bn = 0; bn < 8; bn++) {
            oacc[bn][0] *= fac0; oacc[bn][1] *= fac0;
            oacc[bn][2] *= fac1; oacc[bn][3] *= fac1;
        }

#pragma unroll
        for (int bn = 0; bn < 4; bn++) {
            *(uint32_t*)&Ps[wrow + lr][bn * 8 + 2 * lc]     = pkh(p[bn][0], p[bn][1]);
            *(uint32_t*)&Ps[wrow + 8 + lr][bn * 8 + 2 * lc] = pkh(p[bn][2], p[bn][3]);
        }
        __syncwarp();

#pragma unroll
        for (int kk = 0; kk < 32; kk += 16) {
            uint32_t a0, a1, a2, a3;
            ldsm_x4(a0, a1, a2, a3, s2u(&Ps[wrow + l15][kk + lcoff]));
#pragma unroll
            for (int g = 0; g < 4; g++) {
                uint32_t v0, v1, v2, v3;
                ldsm_x4(v0, v1, v2, v3, s2u(&Vs[g * 16 + brow][kk + bcoff]));
                mma_f16(oacc[2 * g],     a0, a1, a2, a3, v0, v1);
                mma_f16(oacc[2 * g + 1], a0, a1, a2, a3, v2, v3);
            }
        }
        __syncthreads();
    }

    const float inv0 = 1.0f / l0;
    const float inv1 = 1.0f / l1;
    const int row0 = r0 + wrow + lr;
    const int row1 = row0 + 8;
#pragma unroll
    for (int bn = 0; bn < 8; bn++) {
        const int col = h * HD + bn * 8 + 2 * lc;
        *(uint32_t*)(g_heads16 + ((size_t)(b * Nn_ + row0) * Dd) + col) =
            pkh(oacc[bn][0] * inv0, oacc[bn][1] * inv0);
        *(uint32_t*)(g_heads16 + ((size_t)(b * Nn_ + row1) * Dd) + col) =
            pkh(oacc[bn][2] * inv1, oacc[bn][3] * inv1);
    }
}

// ---------------------------------------------------------------------------
extern "C" void kernel_launch(void* const* d_in, const int* in_sizes, int n_in,
                              void* d_out, int out_size)
{
    // Resolve inputs BY SIZE (all element counts are distinct):
    const float *x = 0, *W_qkv = 0, *b_qkv = 0, *W_o = 0, *b_o = 0;
    for (int i = 0; i < n_in; i++) {
        const float* p = (const float*)d_in[i];
        switch (in_sizes[i]) {
            case 8388608: x     = p; break;
            case 3145728: W_qkv = p; break;
            case 3072:    b_qkv = p; break;
            case 1048576: W_o   = p; break;
            case 1024:    b_o   = p; break;
            default: break;
        }
    }
    float* out = (float*)d_out;

    const int M = Bb * Nn_;     // 8192

    // Idempotent, capture-safe: allow 61,440 B dynamic smem for the GEMMs
    cudaFuncSetAttribute(sgemm_kernel<1>,
                         cudaFuncAttributeMaxDynamicSharedMemorySize, GEMM_SMEM_BYTES);
    cudaFuncSetAttribute(sgemm_kernel<2>,
                         cudaFuncAttributeMaxDynamicSharedMemorySize, GEMM_SMEM_BYTES);

    // 0) prologue: one-time fp16 conversion (x) and fp16+transpose (weights)
    cvt_x_kernel<<<8388608 / 8 / 256, 256>>>((const float4*)x);
    {
        dim3 g1(3 * Dd / 32, Dd / 32);      // (96, 32)
        wt_kernel<<<g1, 256>>>(W_qkv, 3 * Dd, Dd, 1);
        dim3 g2(Dd / 32, Dd / 32);          // (32, 32)
        wt_kernel<<<g2, 256>>>(W_o, Dd, Dd, 2);
    }

    // 1) QKV projection (fp16 mma, 64x64 warp tile) + scatter
    {
        dim3 grid(3 * Dd / 128, M / 256);   // (24, 32)
        sgemm_kernel<1><<<grid, 256, GEMM_SMEM_BYTES>>>(b_qkv, (float*)0,
                                                        M, 3 * Dd, Dd);
    }

    // 2) Attention (fp16 mma flash)
    {
        dim3 grid(Nn_ / 64, Bb * Hh);       // (16, 128)
        attn_mma_kernel<<<grid, 128>>>();
    }

    // 3) Output projection
    {
        dim3 grid(Dd / 128, M / 256);       // (8, 32)
        sgemm_kernel<2><<<grid, 256, GEMM_SMEM_BYTES>>>(b_o, out, M, Dd, Dd);
    }
}

// round 17
// speedup vs baseline: 1.2146x; 1.2146x over previous
#include <cuda_runtime.h>
#include <cuda_fp16.h>
#include <cstdint>

#define Bb 8
#define Nn_ 1024
#define Dd 1024
#define Hh 16
#define HD 64
#define QSCALE 0.125f   // 64^-0.5, exact power of two

// Scratch (device globals: no allocations allowed)
__device__ __half g_x16[Bb * Nn_ * Dd];        // x fp16 [row][k]
__device__ __half g_wq16t[3 * Dd * Dd];        // W_qkv fp16 TRANSPOSED [n][k]
__device__ __half g_wo16t[Dd * Dd];            // W_o  fp16 TRANSPOSED [n][k]
__device__ __half g_q16[Bb * Hh * Nn_ * HD];   // Q fp16 [bh][n][d], pre-scaled
__device__ __half g_k16[Bb * Hh * Nn_ * HD];   // K fp16 [bh][n][d]
__device__ __half g_v16[Bb * Hh * Nn_ * HD];   // V fp16 [bh][d][n]  (d-major!)
__device__ __half g_heads16[Bb * Nn_ * Dd];    // heads fp16 [b][n][h*HD+d]

// ---------------------------------------------------------------------------
// helpers
// ---------------------------------------------------------------------------
__device__ __forceinline__ uint32_t pkh(float a, float b) {   // {lo=a, hi=b}
    uint32_t r;
    asm("cvt.rn.f16x2.f32 %0, %1, %2;" : "=r"(r) : "f"(b), "f"(a));
    return r;
}

__device__ __forceinline__ void mma_f16(float c[4],
                                        uint32_t a0, uint32_t a1,
                                        uint32_t a2, uint32_t a3,
                                        uint32_t b0, uint32_t b1) {
    asm volatile(
        "mma.sync.aligned.m16n8k16.row.col.f32.f16.f16.f32 "
        "{%0,%1,%2,%3}, {%4,%5,%6,%7}, {%8,%9}, {%0,%1,%2,%3};"
        : "+f"(c[0]), "+f"(c[1]), "+f"(c[2]), "+f"(c[3])
        : "r"(a0), "r"(a1), "r"(a2), "r"(a3), "r"(b0), "r"(b1));
}

__device__ __forceinline__ uint32_t s2u(const void* p) {
    return (uint32_t)__cvta_generic_to_shared(p);
}

__device__ __forceinline__ void ldsm_x4(uint32_t& r0, uint32_t& r1,
                                        uint32_t& r2, uint32_t& r3,
                                        uint32_t addr) {
    asm volatile("ldmatrix.sync.aligned.m8n8.x4.shared.b16 {%0,%1,%2,%3}, [%4];"
                 : "=r"(r0), "=r"(r1), "=r"(r2), "=r"(r3) : "r"(addr));
}

__device__ __forceinline__ void cp16(void* dst, const void* src) {
    uint32_t d = s2u(dst);
    asm volatile("cp.async.cg.shared.global [%0], [%1], 16;" :: "r"(d), "l"(src));
}
__device__ __forceinline__ void cp_commit() {
    asm volatile("cp.async.commit_group;");
}
template <int N_>
__device__ __forceinline__ void cp_wait() {
    asm volatile("cp.async.wait_group %0;" :: "n"(N_));
}

// ---------------------------------------------------------------------------
// Prologue: x -> fp16 (elementwise; 8 floats per thread)
// ---------------------------------------------------------------------------
__global__ __launch_bounds__(256)
void cvt_x_kernel(const float4* __restrict__ in)
{
    int i = blockIdx.x * blockDim.x + threadIdx.x;   // 0 .. 1M-1
    float4 v0 = in[2 * i];
    float4 v1 = in[2 * i + 1];
    ((uint4*)g_x16)[i] = make_uint4(pkh(v0.x, v0.y), pkh(v0.z, v0.w),
                                    pkh(v1.x, v1.y), pkh(v1.z, v1.w));
}

// ---------------------------------------------------------------------------
// Prologue: W [K][N] fp32 -> Wt [N][K] fp16 (tiled transpose)
// which: 1 -> g_wq16t, 2 -> g_wo16t
// ---------------------------------------------------------------------------
__global__ __launch_bounds__(256)
void wt_kernel(const float* __restrict__ W, int N, int Kdim, int which)
{
    __shared__ __half t[32][33];
    __half* Wt = (which == 1) ? g_wq16t : g_wo16t;

    const int n0 = blockIdx.x * 32;
    const int k0 = blockIdx.y * 32;
    const int tx = threadIdx.x & 31;
    const int ty = threadIdx.x >> 5;      // 0..7

#pragma unroll
    for (int i = 0; i < 32; i += 8)
        t[ty + i][tx] = __float2half_rn(W[(size_t)(k0 + ty + i) * N + n0 + tx]);
    __syncthreads();
#pragma unroll
    for (int i = 0; i < 32; i += 8)
        Wt[(size_t)(n0 + ty + i) * Kdim + k0 + tx] = t[tx][ty + i];
}

// ---------------------------------------------------------------------------
// fp16 tensor-core GEMM: R15 structure (128x128 tile, BK=32, 8 warps 2Mx4N)
// with a 3-stage cp.async pipeline (LDGSTS: no prefetch regs, one L1 op).
// Dynamic smem: 3 x (128+128) x 40 halves = 61,440 B -> 2 CTAs/SM.
// MODE 1: A=g_x16, W=g_wq16t; QKV scatter epilogue (q scaled; V d-major)
// MODE 2: A=g_heads16, W=g_wo16t; fp32 C + bias
// ---------------------------------------------------------------------------
#define GEMM_SMEM_BYTES (3 * (128 * 40 + 128 * 40) * 2)

template <int MODE>
__global__ __launch_bounds__(256)
void sgemm_kernel(const float* __restrict__ bias,
                  float* __restrict__ C,
                  int M, int N, int K)
{
    extern __shared__ __half sh[];
    __half* Ah = sh;                       // [3][128][40]
    __half* Bh = sh + 3 * 128 * 40;        // [3][128][40]

    const __half* __restrict__ A16 = (MODE == 1) ? g_x16    : g_heads16;
    const __half* __restrict__ Wt  = (MODE == 1) ? g_wq16t  : g_wo16t;

    const int tid  = threadIdx.x;
    const int lane = tid & 31;
    const int warp = tid >> 5;
    const int warpM = warp & 1;
    const int warpN = warp >> 1;

    const int r0 = blockIdx.y * 128;
    const int c0 = blockIdx.x * 128;

    // loaders: 2 threads per row, 16 halves (= 2 x 16B cp.async) each
    const int a_row = tid >> 1;
    const int a_kc  = (tid & 1) * 16;

    const __half* Aptr = A16 + (size_t)(r0 + a_row) * K + a_kc;
    const __half* Bptr = Wt + (size_t)(c0 + a_row) * K + a_kc;

    // ldmatrix lane constants
    const int l15   = lane & 15;
    const int lcoff = (lane >> 4) * 8;
    const int brow  = (lane & 7) + ((lane >> 4) << 3);
    const int bcoff = ((lane >> 3) & 1) * 8;

    float acc[4][4][4];
#pragma unroll
    for (int i = 0; i < 4; i++)
#pragma unroll
        for (int j = 0; j < 4; j++)
#pragma unroll
            for (int r = 0; r < 4; r++) acc[i][j][r] = 0.0f;

    const int lr = lane >> 2;
    const int lc = lane & 3;

#define CPLOAD(s, k0) do {                                                  \
        __half* da = Ah + (s) * (128 * 40) + a_row * 40 + a_kc;             \
        cp16(da,     Aptr + (k0));                                          \
        cp16(da + 8, Aptr + (k0) + 8);                                      \
        __half* db = Bh + (s) * (128 * 40) + a_row * 40 + a_kc;             \
        cp16(db,     Bptr + (k0));                                          \
        cp16(db + 8, Bptr + (k0) + 8);                                      \
        cp_commit();                                                        \
    } while (0)

    const int NS = K / 32;                 // 32
    CPLOAD(0, 0);
    CPLOAD(1, 32);

    for (int stage = 0; stage < NS; stage++) {
        if (stage + 1 < NS) cp_wait<1>();
        else                cp_wait<0>();
        __syncthreads();
        // Issue stage+2 into its (long-since-consumed) buffer slot.
        if (stage + 2 < NS) CPLOAD((stage + 2) % 3, (stage + 2) * 32);

        const __half* Ax = Ah + (stage % 3) * (128 * 40);
        const __half* Bx = Bh + (stage % 3) * (128 * 40);

#pragma unroll
        for (int kk = 0; kk < 32; kk += 16) {
            uint32_t af[4][4];
#pragma unroll
            for (int am = 0; am < 4; am++)
                ldsm_x4(af[am][0], af[am][1], af[am][2], af[am][3],
                        s2u(Ax + (warpM * 64 + am * 16 + l15) * 40 + kk + lcoff));
#pragma unroll
            for (int g = 0; g < 2; g++) {
                uint32_t b0, b1, b2, b3;
                ldsm_x4(b0, b1, b2, b3,
                        s2u(Bx + (warpN * 32 + g * 16 + brow) * 40 + kk + bcoff));
#pragma unroll
                for (int am = 0; am < 4; am++) {
                    mma_f16(acc[am][2 * g],     af[am][0], af[am][1], af[am][2],
                            af[am][3], b0, b1);
                    mma_f16(acc[am][2 * g + 1], af[am][0], af[am][1], af[am][2],
                            af[am][3], b2, b3);
                }
            }
        }
        // NOTE: no end-of-loop sync needed: next iteration's CPLOAD targets
        // the slot consumed two stages ago, and the top-of-loop sync orders it.
    }
#undef CPLOAD

    __syncthreads();

    // ---- epilogue ----
#pragma unroll
    for (int am = 0; am < 4; am++) {
        const int row0 = r0 + warpM * 64 + am * 16 + lr;
        const int row1 = row0 + 8;
#pragma unroll
        for (int bn = 0; bn < 4; bn++) {
            const int atomcol = c0 + warpN * 32 + bn * 8;
            const int colp = atomcol + lc * 2;
            const float b0v = bias[colp];
            const float b1v = bias[colp + 1];
            float v00 = acc[am][bn][0] + b0v, v01 = acc[am][bn][1] + b1v;
            float v10 = acc[am][bn][2] + b0v, v11 = acc[am][bn][3] + b1v;

            if (MODE == 2) {
                *(float2*)(C + (size_t)row0 * N + colp) = make_float2(v00, v01);
                *(float2*)(C + (size_t)row1 * N + colp) = make_float2(v10, v11);
            } else {
                const int h     = atomcol / 192;
                const int rem   = atomcol % 192;
                const int t     = rem / 64;          // 0=q 1=k 2=v
                const int dbase = (rem % 64) + lc * 2;
                const int b0r = row0 >> 10, n0 = row0 & 1023;
                const int b1r = row1 >> 10, n1 = row1 & 1023;

                if (t == 2) {
                    const size_t vb0 = ((size_t)(b0r * Hh + h) * HD + dbase) * Nn_;
                    const size_t vb1 = ((size_t)(b1r * Hh + h) * HD + dbase) * Nn_;
                    g_v16[vb0 + n0]       = __float2half_rn(v00);
                    g_v16[vb0 + Nn_ + n0] = __float2half_rn(v01);
                    g_v16[vb1 + n1]       = __float2half_rn(v10);
                    g_v16[vb1 + Nn_ + n1] = __float2half_rn(v11);
                } else {
                    __half* dst = (t == 0) ? g_q16 : g_k16;
                    const float sc = (t == 0) ? QSCALE : 1.0f;
                    const size_t off0 = (((size_t)(b0r * Hh + h) << 10) + n0) * HD + dbase;
                    const size_t off1 = (((size_t)(b1r * Hh + h) << 10) + n1) * HD + dbase;
                    *(uint32_t*)(dst + off0) = pkh(v00 * sc, v01 * sc);
                    *(uint32_t*)(dst + off1) = pkh(v10 * sc, v11 * sc);
                }
            }
        }
    }
}

// ---------------------------------------------------------------------------
// fp16 tensor-core flash attention: R15 math, with double-buffered K/V tiles
// + register prefetch of the next tile (one __syncthreads per iteration).
// Static smem 33,792 B -> still 4 CTAs/SM.
// ---------------------------------------------------------------------------
__global__ __launch_bounds__(128, 4)
void attn_mma_kernel()
{
    __shared__ __half Qs[64][72];
    __shared__ __half Ks[2][32][72];
    __shared__ __half Vs[2][64][40];
    __shared__ __half Ps[64][40];

    const int tid  = threadIdx.x;
    const int lane = tid & 31;
    const int warp = tid >> 5;
    const int lr   = lane >> 2;
    const int lc   = lane & 3;

    const int bh = blockIdx.y;
    const int r0 = blockIdx.x * 64;
    const int b  = bh >> 4;
    const int h  = bh & 15;

    const __half* qg = g_q16 + (size_t)bh * Nn_ * HD;    // [n][d]
    const __half* kg = g_k16 + (size_t)bh * Nn_ * HD;    // [n][d]
    const __half* vg = g_v16 + (size_t)bh * HD * Nn_;    // [d][n]

    const int l15   = lane & 15;
    const int lcoff = (lane >> 4) * 8;
    const int brow  = (lane & 7) + ((lane >> 4) << 3);
    const int bcoff = ((lane >> 3) & 1) * 8;

    // per-thread K/V loader coordinates (2 uint4 each)
    const int k_row = tid >> 3;           // 0..15 (second: +16)
    const int k_c8  = (tid & 7) * 8;
    const int v_d   = tid >> 2;           // 0..31 (second: +32)
    const int v_s8  = (tid & 3) * 8;

    // ---- Q tile ----
#pragma unroll
    for (int i = 0; i < 4; i++) {
        int idx4 = i * 128 + tid;
        int row  = idx4 >> 3;
        int c8   = (idx4 & 7) * 8;
        *(uint4*)&Qs[row][c8] = *(const uint4*)(qg + (size_t)(r0 + row) * HD + c8);
    }

    float oacc[8][4];
#pragma unroll
    for (int bn = 0; bn < 8; bn++)
#pragma unroll
        for (int r = 0; r < 4; r++) oacc[bn][r] = 0.0f;
    float m0 = -3.0e38f, m1 = -3.0e38f, l0 = 0.0f, l1 = 0.0f;

    const int wrow = warp * 16;

    uint4 pk0, pk1, pv0, pv1;

#define AGLOAD(kt) do {                                                     \
        const int c0_ = (kt) * 32;                                          \
        pk0 = *(const uint4*)(kg + (size_t)(c0_ + k_row) * HD + k_c8);      \
        pk1 = *(const uint4*)(kg + (size_t)(c0_ + k_row + 16) * HD + k_c8); \
        pv0 = *(const uint4*)(vg + (size_t)v_d * Nn_ + c0_ + v_s8);         \
        pv1 = *(const uint4*)(vg + (size_t)(v_d + 32) * Nn_ + c0_ + v_s8);  \
    } while (0)

#define ASTORE(buf) do {                                                    \
        *(uint4*)&Ks[buf][k_row][k_c8]      = pk0;                          \
        *(uint4*)&Ks[buf][k_row + 16][k_c8] = pk1;                          \
        *(uint4*)&Vs[buf][v_d][v_s8]        = pv0;                          \
        *(uint4*)&Vs[buf][v_d + 32][v_s8]   = pv1;                          \
    } while (0)

    AGLOAD(0);
    ASTORE(0);
    __syncthreads();

    int buf = 0;
    for (int kt = 0; kt < Nn_ / 32; kt++) {
        if (kt + 1 < Nn_ / 32) AGLOAD(kt + 1);

        // ---- S = Q @ K^T ----
        float sacc[4][4];
#pragma unroll
        for (int bn = 0; bn < 4; bn++)
#pragma unroll
            for (int r = 0; r < 4; r++) sacc[bn][r] = 0.0f;

#pragma unroll
        for (int kk = 0; kk < 64; kk += 16) {
            uint32_t a0, a1, a2, a3;
            ldsm_x4(a0, a1, a2, a3, s2u(&Qs[wrow + l15][kk + lcoff]));
            uint32_t k0r, k1r, k2r, k3r;
            ldsm_x4(k0r, k1r, k2r, k3r, s2u(&Ks[buf][brow][kk + bcoff]));
            mma_f16(sacc[0], a0, a1, a2, a3, k0r, k1r);
            mma_f16(sacc[1], a0, a1, a2, a3, k2r, k3r);
            ldsm_x4(k0r, k1r, k2r, k3r, s2u(&Ks[buf][16 + brow][kk + bcoff]));
            mma_f16(sacc[2], a0, a1, a2, a3, k0r, k1r);
            mma_f16(sacc[3], a0, a1, a2, a3, k2r, k3r);
        }

        // ---- online softmax ----
        float rmax0 = -3.0e38f, rmax1 = -3.0e38f;
#pragma unroll
        for (int bn = 0; bn < 4; bn++) {
            rmax0 = fmaxf(rmax0, fmaxf(sacc[bn][0], sacc[bn][1]));
            rmax1 = fmaxf(rmax1, fmaxf(sacc[bn][2], sacc[bn][3]));
        }
        rmax0 = fmaxf(rmax0, __shfl_xor_sync(0xffffffffu, rmax0, 1));
        rmax0 = fmaxf(rmax0, __shfl_xor_sync(0xffffffffu, rmax0, 2));
        rmax1 = fmaxf(rmax1, __shfl_xor_sync(0xffffffffu, rmax1, 1));
        rmax1 = fmaxf(rmax1, __shfl_xor_sync(0xffffffffu, rmax1, 2));

        const float newm0 = fmaxf(m0, rmax0);
        const float newm1 = fmaxf(m1, rmax1);
        const float fac0  = __expf(m0 - newm0);
        const float fac1  = __expf(m1 - newm1);

        float p[4][4];
        float rsum0 = 0.0f, rsum1 = 0.0f;
#pragma unroll
        for (int bn = 0; bn < 4; bn++) {
            p[bn][0] = __expf(sacc[bn][0] - newm0);
            p[bn][1] = __expf(sacc[bn][1] - newm0);
            p[bn][2] = __expf(sacc[bn][2] - newm1);
            p[bn][3] = __expf(sacc[bn][3] - newm1);
            rsum0 += p[bn][0] + p[bn][1];
            rsum1 += p[bn][2] + p[bn][3];
        }
        rsum0 += __shfl_xor_sync(0xffffffffu, rsum0, 1);
        rsum0 += __shfl_xor_sync(0xffffffffu, rsum0, 2);
        rsum1 += __shfl_xor_sync(0xffffffffu, rsum1, 1);
        rsum1 += __shfl_xor_sync(0xffffffffu, rsum1, 2);

        l0 = l0 * fac0 + rsum0;  m0 = newm0;
        l1 = l1 * fac1 + rsum1;  m1 = newm1;
#pragma unroll
        for (int bn = 0; bn < 8; bn++) {
            oacc[bn][0] *= fac0; oacc[bn][1] *= fac0;
            oacc[bn][2] *= fac1; oacc[bn][3] *= fac1;
        }

        // ---- store P (per-warp-private rows) ----
#pragma unroll
        for (int bn = 0; bn < 4; bn++) {
            *(uint32_t*)&Ps[wrow + lr][bn * 8 + 2 * lc]     = pkh(p[bn][0], p[bn][1]);
            *(uint32_t*)&Ps[wrow + 8 + lr][bn * 8 + 2 * lc] = pkh(p[bn][2], p[bn][3]);
        }
        __syncwarp();

        // ---- O += P @ V ----
#pragma unroll
        for (int kk = 0; kk < 32; kk += 16) {
            uint32_t a0, a1, a2, a3;
            ldsm_x4(a0, a1, a2, a3, s2u(&Ps[wrow + l15][kk + lcoff]));
#pragma unroll
            for (int g = 0; g < 4; g++) {
                uint32_t v0, v1, v2, v3;
                ldsm_x4(v0, v1, v2, v3, s2u(&Vs[buf][g * 16 + brow][kk + bcoff]));
                mma_f16(oacc[2 * g],     a0, a1, a2, a3, v0, v1);
                mma_f16(oacc[2 * g + 1], a0, a1, a2, a3, v2, v3);
            }
        }

        if (kt + 1 < Nn_ / 32) ASTORE(buf ^ 1);
        __syncthreads();
        buf ^= 1;
    }
#undef AGLOAD
#undef ASTORE

    // ---- finalize ----
    const float inv0 = 1.0f / l0;
    const float inv1 = 1.0f / l1;
    const int row0 = r0 + wrow + lr;
    const int row1 = row0 + 8;
#pragma unroll
    for (int bn = 0; bn < 8; bn++) {
        const int col = h * HD + bn * 8 + 2 * lc;
        *(uint32_t*)(g_heads16 + ((size_t)(b * Nn_ + row0) * Dd) + col) =
            pkh(oacc[bn][0] * inv0, oacc[bn][1] * inv0);
        *(uint32_t*)(g_heads16 + ((size_t)(b * Nn_ + row1) * Dd) + col) =
            pkh(oacc[bn][2] * inv1, oacc[bn][3] * inv1);
    }
}

// ---------------------------------------------------------------------------
extern "C" void kernel_launch(void* const* d_in, const int* in_sizes, int n_in,
                              void* d_out, int out_size)
{
    // Resolve inputs BY SIZE (all element counts are distinct):
    const float *x = 0, *W_qkv = 0, *b_qkv = 0, *W_o = 0, *b_o = 0;
    for (int i = 0; i < n_in; i++) {
        const float* p = (const float*)d_in[i];
        switch (in_sizes[i]) {
            case 8388608: x     = p; break;
            case 3145728: W_qkv = p; break;
            case 3072:    b_qkv = p; break;
            case 1048576: W_o   = p; break;
            case 1024:    b_o   = p; break;
            default: break;
        }
    }
    float* out = (float*)d_out;

    const int M = Bb * Nn_;     // 8192

    // Idempotent, capture-safe: allow 61,440 B dynamic smem for the GEMMs
    cudaFuncSetAttribute(sgemm_kernel<1>,
                         cudaFuncAttributeMaxDynamicSharedMemorySize, GEMM_SMEM_BYTES);
    cudaFuncSetAttribute(sgemm_kernel<2>,
                         cudaFuncAttributeMaxDynamicSharedMemorySize, GEMM_SMEM_BYTES);

    // 0) prologue: one-time fp16 conversion (x) and fp16+transpose (weights)
    cvt_x_kernel<<<8388608 / 8 / 256, 256>>>((const float4*)x);
    {
        dim3 g1(3 * Dd / 32, Dd / 32);      // (96, 32)
        wt_kernel<<<g1, 256>>>(W_qkv, 3 * Dd, Dd, 1);
        dim3 g2(Dd / 32, Dd / 32);          // (32, 32)
        wt_kernel<<<g2, 256>>>(W_o, Dd, Dd, 2);
    }

    // 1) QKV projection (fp16 mma, cp.async 3-stage) + scatter
    {
        dim3 grid(3 * Dd / 128, M / 128);   // (24, 64)
        sgemm_kernel<1><<<grid, 256, GEMM_SMEM_BYTES>>>(b_qkv, (float*)0,
                                                        M, 3 * Dd, Dd);
    }

    // 2) Attention (fp16 mma flash, double-buffered K/V prefetch)
    {
        dim3 grid(Nn_ / 64, Bb * Hh);       // (16, 128)
        attn_mma_kernel<<<grid, 128>>>();
    }

    // 3) Output projection
    {
        dim3 grid(Dd / 128, M / 128);       // (8, 64)
        sgemm_kernel<2><<<grid, 256, GEMM_SMEM_BYTES>>>(b_o, out, M, Dd, Dd);
    }
}